// round 1
// baseline (speedup 1.0000x reference)
#include <cuda_runtime.h>
#include <cuda_bf16.h>

#define NEG (-1e9f)

__device__ __forceinline__ void fma2(float2& d, float2 a, float2 b) {
    asm("fma.rn.f32x2 %0, %1, %2, %0;"
        : "+l"(reinterpret_cast<unsigned long long&>(d))
        : "l"(reinterpret_cast<unsigned long long&>(a)),
          "l"(reinterpret_cast<unsigned long long&>(b)));
}

// B=8, S=2048, D=64. Tile: 64 queries x 64 keys, 256 threads (16x16),
// each thread owns 4x4 fragments (rows tr+16i, cols tc+16j).
__global__ void __launch_bounds__(256, 2)
attn_kernel(const float* __restrict__ Q, const float* __restrict__ K,
            const float* __restrict__ V, const float* __restrict__ MQ,
            const float* __restrict__ MK, const float* __restrict__ MV,
            float* __restrict__ out) {
    __shared__ float4 Qs4[64 * 16];   // Q tile, plain [r][k4]
    __shared__ float4 KP4[64 * 16];   // K tile (XOR-swizzled), reused for P (plain)
    __shared__ float4 Vt4[64 * 16];   // V^T tile (XOR-swizzled): [d][c]
    float* KPf = reinterpret_cast<float*>(KP4);
    float* Vtf = reinterpret_cast<float*>(Vt4);

    const int tid = threadIdx.x;
    const int tc  = tid & 15;
    const int tr  = tid >> 4;
    const int b   = blockIdx.y;
    const int q0  = blockIdx.x * 64;
    const long base = (long)b * 2048;

    // ---- load Q tile (once) ----
#pragma unroll
    for (int t = 0; t < 4; t++) {
        int idx = tid + 256 * t;
        int r = idx >> 4, k4 = idx & 15;
        Qs4[idx] = reinterpret_cast<const float4*>(Q + (base + q0 + r) * 64)[k4];
    }
    float mqv[4];
#pragma unroll
    for (int i = 0; i < 4; i++) mqv[i] = MQ[base + q0 + tr + 16 * i];

    float m_[4], l_[4];
    float2 acc[4][2];
#pragma unroll
    for (int i = 0; i < 4; i++) {
        m_[i] = -INFINITY; l_[i] = 0.f;
        acc[i][0] = make_float2(0.f, 0.f);
        acc[i][1] = make_float2(0.f, 0.f);
    }
    __syncthreads();

    for (int kt = 0; kt < 32; ++kt) {
        const int k0 = kt * 64;

        // ---- load K tile (swizzled) + V tile transposed (swizzled, * mask_v) ----
#pragma unroll
        for (int t = 0; t < 4; t++) {
            int idx = tid + 256 * t;
            int c = idx >> 4, k4 = idx & 15;
            const float4 kv = reinterpret_cast<const float4*>(K + (base + k0 + c) * 64)[k4];
            KP4[c * 16 + (k4 ^ (c & 15))] = kv;

            float4 vv = reinterpret_cast<const float4*>(V + (base + k0 + c) * 64)[k4];
            const float mvv = MV[base + k0 + c];
            vv.x *= mvv; vv.y *= mvv; vv.z *= mvv; vv.w *= mvv;
            const int d0 = k4 * 4;
            const int cq = c >> 2, cl = c & 3;
            Vtf[(d0 + 0) * 64 + ((cq ^ ((d0 + 0) & 15)) << 2) + cl] = vv.x;
            Vtf[(d0 + 1) * 64 + ((cq ^ ((d0 + 1) & 15)) << 2) + cl] = vv.y;
            Vtf[(d0 + 2) * 64 + ((cq ^ ((d0 + 2) & 15)) << 2) + cl] = vv.z;
            Vtf[(d0 + 3) * 64 + ((cq ^ ((d0 + 3) & 15)) << 2) + cl] = vv.w;
        }
        float mkv[4];
#pragma unroll
        for (int j = 0; j < 4; j++) mkv[j] = MK[base + k0 + tc + 16 * j];
        __syncthreads();

        // ---- S = Q K^T fragment (4x4 per thread, packed f32x2 FMA) ----
        float2 s2[4][2];
#pragma unroll
        for (int i = 0; i < 4; i++) { s2[i][0] = make_float2(0.f, 0.f); s2[i][1] = make_float2(0.f, 0.f); }

#pragma unroll
        for (int kc = 0; kc < 16; kc++) {
            float4 qf[4], kf[4];
#pragma unroll
            for (int i = 0; i < 4; i++) qf[i] = Qs4[(tr + 16 * i) * 16 + kc];
            const int sw = kc ^ tc;
#pragma unroll
            for (int j = 0; j < 4; j++) kf[j] = KP4[(tc + 16 * j) * 16 + sw];

#define S_STEP(COMP)                                                        \
            {                                                               \
                float2 bp0 = make_float2(kf[0].COMP, kf[1].COMP);           \
                float2 bp1 = make_float2(kf[2].COMP, kf[3].COMP);           \
                _Pragma("unroll")                                           \
                for (int i = 0; i < 4; i++) {                               \
                    float2 ap = make_float2(qf[i].COMP, qf[i].COMP);        \
                    fma2(s2[i][0], ap, bp0);                                \
                    fma2(s2[i][1], ap, bp1);                                \
                }                                                           \
            }
            S_STEP(x) S_STEP(y) S_STEP(z) S_STEP(w)
#undef S_STEP
        }

        // ---- online softmax (rows tr+16i, reduce across 16 lanes) ----
        float p[4][4];
#pragma unroll
        for (int i = 0; i < 4; i++) {
            float sv[4] = { s2[i][0].x, s2[i][0].y, s2[i][1].x, s2[i][1].y };
#pragma unroll
            for (int j = 0; j < 4; j++)
                sv[j] = sv[j] * 0.125f + (1.0f - mqv[i] * mkv[j]) * NEG;

            float tm = fmaxf(fmaxf(sv[0], sv[1]), fmaxf(sv[2], sv[3]));
#pragma unroll
            for (int off = 8; off > 0; off >>= 1)
                tm = fmaxf(tm, __shfl_xor_sync(0xffffffffu, tm, off, 16));

            const float mnew = fmaxf(m_[i], tm);
            const float corr = (m_[i] > -1e30f) ? __expf(m_[i] - mnew) : 0.f;

            float ls = 0.f;
#pragma unroll
            for (int j = 0; j < 4; j++) { p[i][j] = __expf(sv[j] - mnew); ls += p[i][j]; }
#pragma unroll
            for (int off = 8; off > 0; off >>= 1)
                ls += __shfl_xor_sync(0xffffffffu, ls, off, 16);

            l_[i] = l_[i] * corr + ls;
            m_[i] = mnew;
            acc[i][0].x *= corr; acc[i][0].y *= corr;
            acc[i][1].x *= corr; acc[i][1].y *= corr;
        }

        __syncthreads();   // everyone done reading K tile
        // ---- write P into KP buffer (plain layout) ----
#pragma unroll
        for (int i = 0; i < 4; i++)
#pragma unroll
            for (int j = 0; j < 4; j++)
                KPf[(tr + 16 * i) * 64 + tc + 16 * j] = p[i][j];
        __syncthreads();

        // ---- O += P @ V  (V^T in smem, inner dim c) ----
#pragma unroll
        for (int kc = 0; kc < 16; kc++) {
            float4 pf[4], vf[4];
#pragma unroll
            for (int i = 0; i < 4; i++) pf[i] = KP4[(tr + 16 * i) * 16 + kc];
            const int sw = kc ^ tc;
#pragma unroll
            for (int j = 0; j < 4; j++) vf[j] = Vt4[(tc + 16 * j) * 16 + sw];

#define PV_STEP(COMP)                                                       \
            {                                                               \
                float2 vp0 = make_float2(vf[0].COMP, vf[1].COMP);           \
                float2 vp1 = make_float2(vf[2].COMP, vf[3].COMP);           \
                _Pragma("unroll")                                           \
                for (int i = 0; i < 4; i++) {                               \
                    float2 ap = make_float2(pf[i].COMP, pf[i].COMP);        \
                    fma2(acc[i][0], ap, vp0);                               \
                    fma2(acc[i][1], ap, vp1);                               \
                }                                                           \
            }
            PV_STEP(x) PV_STEP(y) PV_STEP(z) PV_STEP(w)
#undef PV_STEP
        }
        __syncthreads();   // done reading P/V before next tile load
    }

    // ---- epilogue: O / l ----
#pragma unroll
    for (int i = 0; i < 4; i++) {
        const float inv = 1.0f / l_[i];
        const long row = base + q0 + tr + 16 * i;
        out[row * 64 + tc +  0] = acc[i][0].x * inv;
        out[row * 64 + tc + 16] = acc[i][0].y * inv;
        out[row * 64 + tc + 32] = acc[i][1].x * inv;
        out[row * 64 + tc + 48] = acc[i][1].y * inv;
    }
}

extern "C" void kernel_launch(void* const* d_in, const int* in_sizes, int n_in,
                              void* d_out, int out_size) {
    const float* Q  = (const float*)d_in[0];
    const float* K  = (const float*)d_in[1];
    const float* V  = (const float*)d_in[2];
    const float* MQ = (const float*)d_in[3];
    const float* MK = (const float*)d_in[4];
    const float* MV = (const float*)d_in[5];
    float* out = (float*)d_out;

    dim3 grid(2048 / 64, 8);   // (q tiles, batch)
    attn_kernel<<<grid, 256>>>(Q, K, V, MQ, MK, MV, out);
}

// round 2
// speedup vs baseline: 1.0030x; 1.0030x over previous
#include <cuda_runtime.h>
#include <cuda_bf16.h>

#define NEG (-1e9f)

__device__ __forceinline__ void fma2(float2& d, float2 a, float2 b) {
    asm("fma.rn.f32x2 %0, %1, %2, %0;"
        : "+l"(reinterpret_cast<unsigned long long&>(d))
        : "l"(reinterpret_cast<unsigned long long&>(a)),
          "l"(reinterpret_cast<unsigned long long&>(b)));
}

// B=8, S=2048, D=64. Tile: 64 queries x 64 keys, 256 threads (16x16),
// each thread owns 4x4 fragments (rows tr+16i, cols tc+16j).
__global__ void __launch_bounds__(256, 2)
attn_kernel(const float* __restrict__ Q, const float* __restrict__ K,
            const float* __restrict__ V, const float* __restrict__ MQ,
            const float* __restrict__ MK, const float* __restrict__ MV,
            float* __restrict__ out) {
    __shared__ float4 Qs4[64 * 16];   // Q tile, plain [r][k4]
    __shared__ float4 KP4[64 * 16];   // K tile (XOR-swizzled), reused for P (plain)
    __shared__ float4 Vt4[64 * 16];   // V^T tile (XOR-swizzled): [d][c]
    float* KPf = reinterpret_cast<float*>(KP4);
    float* Vtf = reinterpret_cast<float*>(Vt4);

    const int tid = threadIdx.x;
    const int tc  = tid & 15;
    const int tr  = tid >> 4;
    const int b   = blockIdx.y;
    const int q0  = blockIdx.x * 64;
    const long base = (long)b * 2048;

    // ---- load Q tile (once) ----
#pragma unroll
    for (int t = 0; t < 4; t++) {
        int idx = tid + 256 * t;
        int r = idx >> 4, k4 = idx & 15;
        Qs4[idx] = reinterpret_cast<const float4*>(Q + (base + q0 + r) * 64)[k4];
    }
    float mqv[4];
#pragma unroll
    for (int i = 0; i < 4; i++) mqv[i] = MQ[base + q0 + tr + 16 * i];

    float m_[4], l_[4];
    float2 acc[4][2];
#pragma unroll
    for (int i = 0; i < 4; i++) {
        m_[i] = -INFINITY; l_[i] = 0.f;
        acc[i][0] = make_float2(0.f, 0.f);
        acc[i][1] = make_float2(0.f, 0.f);
    }
    __syncthreads();

    for (int kt = 0; kt < 32; ++kt) {
        const int k0 = kt * 64;

        // ---- load K tile (swizzled) + V tile transposed (swizzled, * mask_v) ----
#pragma unroll
        for (int t = 0; t < 4; t++) {
            int idx = tid + 256 * t;
            int c = idx >> 4, k4 = idx & 15;
            const float4 kv = reinterpret_cast<const float4*>(K + (base + k0 + c) * 64)[k4];
            KP4[c * 16 + (k4 ^ (c & 15))] = kv;

            float4 vv = reinterpret_cast<const float4*>(V + (base + k0 + c) * 64)[k4];
            const float mvv = MV[base + k0 + c];
            vv.x *= mvv; vv.y *= mvv; vv.z *= mvv; vv.w *= mvv;
            const int d0 = k4 * 4;
            const int cq = c >> 2, cl = c & 3;
            Vtf[(d0 + 0) * 64 + ((cq ^ ((d0 + 0) & 15)) << 2) + cl] = vv.x;
            Vtf[(d0 + 1) * 64 + ((cq ^ ((d0 + 1) & 15)) << 2) + cl] = vv.y;
            Vtf[(d0 + 2) * 64 + ((cq ^ ((d0 + 2) & 15)) << 2) + cl] = vv.z;
            Vtf[(d0 + 3) * 64 + ((cq ^ ((d0 + 3) & 15)) << 2) + cl] = vv.w;
        }
        float mkv[4];
#pragma unroll
        for (int j = 0; j < 4; j++) mkv[j] = MK[base + k0 + tc + 16 * j];
        __syncthreads();

        // ---- S = Q K^T fragment (4x4 per thread, packed f32x2 FMA) ----
        float2 s2[4][2];
#pragma unroll
        for (int i = 0; i < 4; i++) { s2[i][0] = make_float2(0.f, 0.f); s2[i][1] = make_float2(0.f, 0.f); }

#pragma unroll
        for (int kc = 0; kc < 16; kc++) {
            float4 qf[4], kf[4];
#pragma unroll
            for (int i = 0; i < 4; i++) qf[i] = Qs4[(tr + 16 * i) * 16 + kc];
            const int sw = kc ^ tc;
#pragma unroll
            for (int j = 0; j < 4; j++) kf[j] = KP4[(tc + 16 * j) * 16 + sw];

#define S_STEP(COMP)                                                        \
            {                                                               \
                float2 bp0 = make_float2(kf[0].COMP, kf[1].COMP);           \
                float2 bp1 = make_float2(kf[2].COMP, kf[3].COMP);           \
                _Pragma("unroll")                                           \
                for (int i = 0; i < 4; i++) {                               \
                    float2 ap = make_float2(qf[i].COMP, qf[i].COMP);        \
                    fma2(s2[i][0], ap, bp0);                                \
                    fma2(s2[i][1], ap, bp1);                                \
                }                                                           \
            }
            S_STEP(x) S_STEP(y) S_STEP(z) S_STEP(w)
#undef S_STEP
        }

        // ---- online softmax (rows tr+16i, reduce across 16 lanes) ----
        float p[4][4];
#pragma unroll
        for (int i = 0; i < 4; i++) {
            float sv[4] = { s2[i][0].x, s2[i][0].y, s2[i][1].x, s2[i][1].y };
#pragma unroll
            for (int j = 0; j < 4; j++)
                sv[j] = sv[j] * 0.125f + (1.0f - mqv[i] * mkv[j]) * NEG;

            float tm = fmaxf(fmaxf(sv[0], sv[1]), fmaxf(sv[2], sv[3]));
#pragma unroll
            for (int off = 8; off > 0; off >>= 1)
                tm = fmaxf(tm, __shfl_xor_sync(0xffffffffu, tm, off, 16));

            const float mnew = fmaxf(m_[i], tm);
            const float corr = (m_[i] > -1e30f) ? __expf(m_[i] - mnew) : 0.f;

            float ls = 0.f;
#pragma unroll
            for (int j = 0; j < 4; j++) { p[i][j] = __expf(sv[j] - mnew); ls += p[i][j]; }
#pragma unroll
            for (int off = 8; off > 0; off >>= 1)
                ls += __shfl_xor_sync(0xffffffffu, ls, off, 16);

            l_[i] = l_[i] * corr + ls;
            m_[i] = mnew;
            acc[i][0].x *= corr; acc[i][0].y *= corr;
            acc[i][1].x *= corr; acc[i][1].y *= corr;
        }

        __syncthreads();   // everyone done reading K tile
        // ---- write P into KP buffer (plain layout) ----
#pragma unroll
        for (int i = 0; i < 4; i++)
#pragma unroll
            for (int j = 0; j < 4; j++)
                KPf[(tr + 16 * i) * 64 + tc + 16 * j] = p[i][j];
        __syncthreads();

        // ---- O += P @ V  (V^T in smem, inner dim c) ----
#pragma unroll
        for (int kc = 0; kc < 16; kc++) {
            float4 pf[4], vf[4];
#pragma unroll
            for (int i = 0; i < 4; i++) pf[i] = KP4[(tr + 16 * i) * 16 + kc];
            const int sw = kc ^ tc;
#pragma unroll
            for (int j = 0; j < 4; j++) vf[j] = Vt4[(tc + 16 * j) * 16 + sw];

#define PV_STEP(COMP)                                                       \
            {                                                               \
                float2 vp0 = make_float2(vf[0].COMP, vf[1].COMP);           \
                float2 vp1 = make_float2(vf[2].COMP, vf[3].COMP);           \
                _Pragma("unroll")                                           \
                for (int i = 0; i < 4; i++) {                               \
                    float2 ap = make_float2(pf[i].COMP, pf[i].COMP);        \
                    fma2(acc[i][0], ap, vp0);                               \
                    fma2(acc[i][1], ap, vp1);                               \
                }                                                           \
            }
            PV_STEP(x) PV_STEP(y) PV_STEP(z) PV_STEP(w)
#undef PV_STEP
        }
        __syncthreads();   // done reading P/V before next tile load
    }

    // ---- epilogue: O / l ----
#pragma unroll
    for (int i = 0; i < 4; i++) {
        const float inv = 1.0f / l_[i];
        const long row = base + q0 + tr + 16 * i;
        out[row * 64 + tc +  0] = acc[i][0].x * inv;
        out[row * 64 + tc + 16] = acc[i][0].y * inv;
        out[row * 64 + tc + 32] = acc[i][1].x * inv;
        out[row * 64 + tc + 48] = acc[i][1].y * inv;
    }
}

extern "C" void kernel_launch(void* const* d_in, const int* in_sizes, int n_in,
                              void* d_out, int out_size) {
    const float* Q  = (const float*)d_in[0];
    const float* K  = (const float*)d_in[1];
    const float* V  = (const float*)d_in[2];
    const float* MQ = (const float*)d_in[3];
    const float* MK = (const float*)d_in[4];
    const float* MV = (const float*)d_in[5];
    float* out = (float*)d_out;

    dim3 grid(2048 / 64, 8);   // (q tiles, batch)
    attn_kernel<<<grid, 256>>>(Q, K, V, MQ, MK, MV, out);
}

// round 4
// speedup vs baseline: 4.7895x; 4.7752x over previous
#include <cuda_runtime.h>
#include <cuda_bf16.h>
#include <cstdint>

#define L2E   1.44269504088896340736f
#define C1    (0.125f * L2E)
#define NEGA  (-1e9f * L2E)

// smem byte offsets (union: Q staging overlays K/V tile buffers)
#define SQHI 0
#define SQLO 18432
#define SKHI 0
#define SKLO 9216
#define SVHI 18432
#define SVLO 27648
// bf16 row stride = 72 elems (144 B): ldmatrix 8-row bursts hit distinct banks

__device__ __forceinline__ uint32_t smem_u32(const void* p) {
    uint32_t a;
    asm("{ .reg .u64 t; cvta.to.shared.u64 t, %1; cvt.u32.u64 %0, t; }" : "=r"(a) : "l"(p));
    return a;
}
__device__ __forceinline__ float ex2f(float x) {
    float r; asm("ex2.approx.ftz.f32 %0, %1;" : "=f"(r) : "f"(x)); return r;
}
__device__ __forceinline__ void sts64(uint32_t a, uint32_t x, uint32_t y) {
    asm volatile("st.shared.v2.b32 [%0], {%1,%2};" :: "r"(a), "r"(x), "r"(y) : "memory");
}
// split two f32 -> bf16x2 hi word + bf16x2 lo word (elem0 in low half)
__device__ __forceinline__ void split2(float a, float b, uint32_t& hi, uint32_t& lo) {
    __nv_bfloat162 h = __floats2bfloat162_rn(a, b);
    float ra = a - __bfloat162float(h.x);
    float rb = b - __bfloat162float(h.y);
    __nv_bfloat162 l = __floats2bfloat162_rn(ra, rb);
    hi = *reinterpret_cast<const uint32_t*>(&h);
    lo = *reinterpret_cast<const uint32_t*>(&l);
}

#define LDSM_X4(r0, r1, r2, r3, addr) \
    asm volatile("ldmatrix.sync.aligned.m8n8.x4.shared.b16 {%0,%1,%2,%3}, [%4];" \
        : "=r"(r0), "=r"(r1), "=r"(r2), "=r"(r3) : "r"(addr))
#define LDSM_X4T(r0, r1, r2, r3, addr) \
    asm volatile("ldmatrix.sync.aligned.m8n8.x4.trans.shared.b16 {%0,%1,%2,%3}, [%4];" \
        : "=r"(r0), "=r"(r1), "=r"(r2), "=r"(r3) : "r"(addr))

__device__ __forceinline__ void mma16816(float* d, const uint32_t* a, uint32_t b0, uint32_t b1) {
    asm volatile("mma.sync.aligned.m16n8k16.row.col.f32.bf16.bf16.f32 "
        "{%0,%1,%2,%3}, {%4,%5,%6,%7}, {%8,%9}, {%0,%1,%2,%3};"
        : "+f"(d[0]), "+f"(d[1]), "+f"(d[2]), "+f"(d[3])
        : "r"(a[0]), "r"(a[1]), "r"(a[2]), "r"(a[3]), "r"(b0), "r"(b1));
}

// B=8, S=2048, D=64. grid=(16,8), 256 threads = 8 warps x 16 q-rows.
__global__ void __launch_bounds__(256, 1)
attn_mma_kernel(const float* __restrict__ Q, const float* __restrict__ K,
                const float* __restrict__ V, const float* __restrict__ MQ,
                const float* __restrict__ MK, const float* __restrict__ MV,
                float* __restrict__ out) {
    __shared__ __align__(16) unsigned char smbuf[36864];
    __shared__ float mks[64];
    const uint32_t sb = smem_u32(smbuf);

    const int tid  = threadIdx.x;
    const int w    = tid >> 5;
    const int lane = tid & 31;
    const int g    = lane >> 2;       // row-in-8 group
    const int tq   = lane & 3;        // col-pair index
    // ldmatrix per-lane offsets
    const int la_r  = (lane & 7) + (lane & 8);   // A/V pattern row
    const int la_c  = (lane >> 4) << 3;          // A/V pattern col +8
    const int lb_r  = (lane & 7) + ((lane >> 4) << 3);  // K B pattern row
    const int lb_c  = (lane & 8);                       // K B pattern col +8

    const int b  = blockIdx.y;
    const int q0 = blockIdx.x * 128;
    const size_t base = (size_t)b * 2048;

    const float4* Q4 = reinterpret_cast<const float4*>(Q);
    const float4* K4 = reinterpret_cast<const float4*>(K);
    const float4* V4 = reinterpret_cast<const float4*>(V);

    // ---- stage Q (128x64) split into smem ----
#pragma unroll
    for (int t = 0; t < 8; t++) {
        int idx = tid + 256 * t;
        int r = idx >> 4, c4 = idx & 15;
        float4 q = Q4[(base + q0 + r) * 16 + c4];
        uint32_t h0, l0, h1, l1;
        split2(q.x, q.y, h0, l0);
        split2(q.z, q.w, h1, l1);
        uint32_t off = (uint32_t)(r * 144 + c4 * 8);
        sts64(sb + SQHI + off, h0, h1);
        sts64(sb + SQLO + off, l0, l1);
    }
    __syncthreads();

    // ---- load persistent Q fragments (rows 16w..16w+15, 4 k-chunks, hi/lo) ----
    uint32_t qh[4][4], ql[4][4];
#pragma unroll
    for (int kc = 0; kc < 4; kc++) {
        uint32_t off = (uint32_t)((16 * w + la_r) * 144 + (kc * 16 + la_c) * 2);
        LDSM_X4(qh[kc][0], qh[kc][1], qh[kc][2], qh[kc][3], sb + SQHI + off);
        LDSM_X4(ql[kc][0], ql[kc][1], ql[kc][2], ql[kc][3], sb + SQLO + off);
    }

    const float mqa = MQ[base + q0 + 16 * w + g];
    const float mqb = MQ[base + q0 + 16 * w + g + 8];
    const float bqa = -NEGA * mqa;
    const float bqb = -NEGA * mqb;

    float o[8][4];
#pragma unroll
    for (int n = 0; n < 8; n++)
#pragma unroll
        for (int c = 0; c < 4; c++) o[n][c] = 0.f;
    float lr0 = 0.f, lr1 = 0.f;

    // ---- prefetch tile 0 ----
    float4 kreg[4], vreg[4];
    float  mvr[4], mk_in;
#pragma unroll
    for (int t = 0; t < 4; t++) {
        int idx = tid + 256 * t;
        int r = idx >> 4, c4 = idx & 15;
        kreg[t] = K4[(base + r) * 16 + c4];
        vreg[t] = V4[(base + r) * 16 + c4];
        mvr[t]  = MV[base + r];
    }
    mk_in = (tid < 64) ? MK[base + tid] : 0.f;

    for (int kt = 0; kt < 32; kt++) {
        __syncthreads();   // prior tile's smem reads (or Q ldsm) complete

        // ---- store K/V split tiles ----
#pragma unroll
        for (int t = 0; t < 4; t++) {
            int idx = tid + 256 * t;
            int r = idx >> 4, c4 = idx & 15;
            uint32_t off = (uint32_t)(r * 144 + c4 * 8);
            uint32_t h0, l0, h1, l1;
            split2(kreg[t].x, kreg[t].y, h0, l0);
            split2(kreg[t].z, kreg[t].w, h1, l1);
            sts64(sb + SKHI + off, h0, h1);
            sts64(sb + SKLO + off, l0, l1);
            float m = mvr[t];
            split2(vreg[t].x * m, vreg[t].y * m, h0, l0);
            split2(vreg[t].z * m, vreg[t].w * m, h1, l1);
            sts64(sb + SVHI + off, h0, h1);
            sts64(sb + SVLO + off, l0, l1);
        }
        if (tid < 64) mks[tid] = mk_in;
        __syncthreads();

        // ---- S = Q K^T (16 x 64 per warp), 3-split ----
        float s[8][4];
#pragma unroll
        for (int n = 0; n < 8; n++)
#pragma unroll
            for (int c = 0; c < 4; c++) s[n][c] = 0.f;

#pragma unroll
        for (int kc = 0; kc < 4; kc++) {
#pragma unroll
            for (int np = 0; np < 4; np++) {
                uint32_t off = (uint32_t)((np * 16 + lb_r) * 144 + (kc * 16 + lb_c) * 2);
                uint32_t bh0, bh1, bh2, bh3, bl0, bl1, bl2, bl3;
                LDSM_X4(bh0, bh1, bh2, bh3, sb + SKHI + off);
                LDSM_X4(bl0, bl1, bl2, bl3, sb + SKLO + off);
                mma16816(s[2 * np],     qh[kc], bh0, bh1);
                mma16816(s[2 * np],     ql[kc], bh0, bh1);
                mma16816(s[2 * np],     qh[kc], bl0, bl1);
                mma16816(s[2 * np + 1], qh[kc], bh2, bh3);
                mma16816(s[2 * np + 1], ql[kc], bh2, bh3);
                mma16816(s[2 * np + 1], qh[kc], bl2, bl3);
            }
        }

        // ---- softmax (no max-sub; exact mask term) + P fragments ----
        uint32_t ph[4][4], pl[4][4];
#pragma unroll
        for (int n = 0; n < 8; n++) {
            int col0 = 8 * n + 2 * tq;
            float mk0 = mks[col0], mk1 = mks[col0 + 1];
            float t00 = fmaf(bqa, mk0, NEGA);
            float t01 = fmaf(bqa, mk1, NEGA);
            float t10 = fmaf(bqb, mk0, NEGA);
            float t11 = fmaf(bqb, mk1, NEGA);
            float p0 = ex2f(fmaf(s[n][0], C1, t00));
            float p1 = ex2f(fmaf(s[n][1], C1, t01));
            float p2 = ex2f(fmaf(s[n][2], C1, t10));
            float p3 = ex2f(fmaf(s[n][3], C1, t11));
            lr0 += p0 + p1;
            lr1 += p2 + p3;
            split2(p0, p1, ph[n >> 1][(n & 1) * 2],     pl[n >> 1][(n & 1) * 2]);
            split2(p2, p3, ph[n >> 1][(n & 1) * 2 + 1], pl[n >> 1][(n & 1) * 2 + 1]);
        }

        // ---- prefetch next tile (overlaps PV mma) ----
        if (kt < 31) {
            const int k0n = (kt + 1) * 64;
#pragma unroll
            for (int t = 0; t < 4; t++) {
                int idx = tid + 256 * t;
                int r = idx >> 4, c4 = idx & 15;
                kreg[t] = K4[(base + k0n + r) * 16 + c4];
                vreg[t] = V4[(base + k0n + r) * 16 + c4];
                mvr[t]  = MV[base + k0n + r];
            }
            mk_in = (tid < 64) ? MK[base + k0n + tid] : 0.f;
        }

        // ---- O += P V (V via ldmatrix.trans), 3-split ----
#pragma unroll
        for (int kc = 0; kc < 4; kc++) {
#pragma unroll
            for (int dp = 0; dp < 4; dp++) {
                uint32_t off = (uint32_t)((kc * 16 + la_r) * 144 + (dp * 16 + la_c) * 2);
                uint32_t bh0, bh1, bh2, bh3, bl0, bl1, bl2, bl3;
                LDSM_X4T(bh0, bh1, bh2, bh3, sb + SVHI + off);
                LDSM_X4T(bl0, bl1, bl2, bl3, sb + SVLO + off);
                mma16816(o[2 * dp],     ph[kc], bh0, bh1);
                mma16816(o[2 * dp],     pl[kc], bh0, bh1);
                mma16816(o[2 * dp],     ph[kc], bl0, bl1);
                mma16816(o[2 * dp + 1], ph[kc], bh2, bh3);
                mma16816(o[2 * dp + 1], pl[kc], bh2, bh3);
                mma16816(o[2 * dp + 1], ph[kc], bl2, bl3);
            }
        }
    }

    // ---- epilogue: reduce row sums across the 4 lanes sharing a row ----
    lr0 += __shfl_xor_sync(0xffffffffu, lr0, 1);
    lr0 += __shfl_xor_sync(0xffffffffu, lr0, 2);
    lr1 += __shfl_xor_sync(0xffffffffu, lr1, 1);
    lr1 += __shfl_xor_sync(0xffffffffu, lr1, 2);
    const float inv0 = 1.0f / lr0;
    const float inv1 = 1.0f / lr1;

    const size_t row0 = base + q0 + 16 * w + g;
    const size_t row1 = row0 + 8;
#pragma unroll
    for (int n = 0; n < 8; n++) {
        float2 v0 = make_float2(o[n][0] * inv0, o[n][1] * inv0);
        float2 v1 = make_float2(o[n][2] * inv1, o[n][3] * inv1);
        *reinterpret_cast<float2*>(out + row0 * 64 + 8 * n + 2 * tq) = v0;
        *reinterpret_cast<float2*>(out + row1 * 64 + 8 * n + 2 * tq) = v1;
    }
}

extern "C" void kernel_launch(void* const* d_in, const int* in_sizes, int n_in,
                              void* d_out, int out_size) {
    const float* Q  = (const float*)d_in[0];
    const float* K  = (const float*)d_in[1];
    const float* V  = (const float*)d_in[2];
    const float* MQ = (const float*)d_in[3];
    const float* MK = (const float*)d_in[4];
    const float* MV = (const float*)d_in[5];
    float* out = (float*)d_out;

    dim3 grid(16, 8);
    attn_mma_kernel<<<grid, 256>>>(Q, K, V, MQ, MK, MV, out);
}